// round 11
// baseline (speedup 1.0000x reference)
#include <cuda_runtime.h>
#include <math.h>

// ---------------------------------------------------------------------------
// ONE persistent kernel = ONE graph node. 128 CTAs x 256 threads, co-resident
// (grid <= 148 SMs) -> software grid barrier.
//
// Per RK4 f-eval:
//   G1   : partials of A @ W1   (32 N-tiles(128) x split-K4 = 128 jobs)
//   redH : H = tanh(P0+P1+P2+P3+b1)
//   G2   : partials of H @ W2   (25 N-tiles(128) x split-K4 = 100 jobs)
//   upd  : k = sum(P)+b2 ; RK4 state update (+ trajectory store on k4)
//
// GEMM job: C(128x128), 256 threads (2 warps/SMSP for latency hiding),
// per-thread 8x8 via packed fma.rn.f32x2 with diag/anti-diag pairing.
// smem holds A[k][m], B[k][n], and a pair-swapped B copy, so ALL six operand
// groups load as natural ulonglong2 (LDS.128) -> zero packing MOVs.
// Double-buffered smem (48KB), one __syncthreads per 16-k block.
// Cross-CTA global reads use __ldcg (L1 incoherent within one launch).
// ---------------------------------------------------------------------------

#define BATCH   128
#define STATE   3200
#define OHID    4096
#define NSTEPS  192
#define NCTA    128
#define NTHR    256

constexpr float DT  = (float)(8.0 / 191.0);   // matches jnp f64->f32
constexpr float HDT = 0.5f * DT;
constexpr float DT6 = DT / 6.0f;

// -------------------- device scratch (no allocation allowed) ----------------
__device__ __align__(16) float g_embs[BATCH * 2048];
__device__ __align__(16) float g_Y   [BATCH * STATE];
__device__ __align__(16) float g_TMP [BATCH * STATE];
__device__ __align__(16) float g_ACC [BATCH * STATE];
__device__ __align__(16) float g_H   [BATCH * OHID];
__device__ __align__(16) float g_P1  [4 * BATCH * OHID];   // G1 split-K4 partials
__device__ __align__(16) float g_P2  [4 * BATCH * STATE];  // G2 split-K4 partials
__device__ unsigned          g_cnt;
__device__ volatile unsigned g_gen;

// ------------------------------- primitives ---------------------------------
__device__ __forceinline__ float2 upk(unsigned long long v) {
    float2 f;
    asm("mov.b64 {%0, %1}, %2;" : "=f"(f.x), "=f"(f.y) : "l"(v));
    return f;
}
__device__ __forceinline__ void ffma2(unsigned long long& d,
                                      unsigned long long a, unsigned long long b) {
    asm("fma.rn.f32x2 %0, %1, %2, %0;" : "+l"(d) : "l"(a), "l"(b));
}
__device__ __forceinline__ float4 ldcg4(const float* p) {
    return __ldcg(reinterpret_cast<const float4*>(p));
}

// Grid barrier: all 128 CTAs co-resident (1/SM). Fence by every thread makes
// this CTA's writes L2-visible before the arrival is published.
__device__ __forceinline__ void gridbar() {
    __threadfence();
    __syncthreads();
    if (threadIdx.x == 0) {
        const unsigned my = g_gen;
        if (atomicAdd(&g_cnt, 1u) == NCTA - 1u) {
            g_cnt = 0u;
            __threadfence();
            g_gen = my + 1u;
        } else {
            while (g_gen == my) { }
        }
        __threadfence();
    }
    __syncthreads();
}

// ------------------------------ GEMM tile job --------------------------------
// Partial C(128 x 128) = A[:, kbeg : kbeg+16*nblk] @ W[:, n0:n0+128] -> P (raw).
__device__ __forceinline__ void gemm_job(
    const float* __restrict__ A, int lda,
    const float* __restrict__ W, int ldw,
    int kbeg, int nblk, int n0,
    float* __restrict__ P, int ldp,
    float (&As)[2][16][128], float (&Bs)[2][16][128], float (&Bw)[2][16][128])
{
    const int tid = threadIdx.x;
    const int tm  = (tid >> 4) * 8;      // m base (0..120)
    const int tn  = (tid & 15) * 8;      // n base (0..120)
    // A staging: row = tid>>1 (0..127), k-half = (tid&1)*8
    const int arow = tid >> 1;
    const int akh  = (tid & 1) * 8;
    // B staging: k-row = tid>>4 (0..15), col base = (tid&15)*8
    const int brow = tid >> 4;
    const int bcol = (tid & 15) * 8;

    const float* Ap = A + (size_t)arow * lda + kbeg + akh;
    const float* Wp = W + (size_t)(kbeg + brow) * ldw + n0 + bcol;
    const size_t wstep = (size_t)16 * ldw;

    unsigned long long accd[4][4], accx[4][4];
#pragma unroll
    for (int i = 0; i < 4; i++)
#pragma unroll
        for (int j = 0; j < 4; j++) { accd[i][j] = 0ull; accx[i][j] = 0ull; }

    float4 a0, a1, b0, b1;

#define LDG_BLK(bk)                                                \
    do {                                                           \
        const float* Aq = Ap + (bk) * 16;                          \
        a0 = ldcg4(Aq);  a1 = ldcg4(Aq + 4);                       \
        const float* Wq = Wp + (size_t)(bk) * wstep;               \
        b0 = *(const float4*)Wq;                                   \
        b1 = *(const float4*)(Wq + 4);                             \
    } while (0)

#define STS_BLK(nb)                                                \
    do {                                                           \
        As[nb][akh + 0][arow] = a0.x; As[nb][akh + 1][arow] = a0.y;\
        As[nb][akh + 2][arow] = a0.z; As[nb][akh + 3][arow] = a0.w;\
        As[nb][akh + 4][arow] = a1.x; As[nb][akh + 5][arow] = a1.y;\
        As[nb][akh + 6][arow] = a1.z; As[nb][akh + 7][arow] = a1.w;\
        *(float4*)&Bs[nb][brow][bcol]     = b0;                    \
        *(float4*)&Bs[nb][brow][bcol + 4] = b1;                    \
        *(float4*)&Bw[nb][brow][bcol]     = make_float4(b0.y, b0.x, b0.w, b0.z); \
        *(float4*)&Bw[nb][brow][bcol + 4] = make_float4(b1.y, b1.x, b1.w, b1.z); \
    } while (0)

    LDG_BLK(0);
    STS_BLK(0);
    __syncthreads();

    for (int bk = 0; bk < nblk; bk++) {
        const int cur = bk & 1;
        const bool more = (bk + 1) < nblk;
        if (more) LDG_BLK(bk + 1);

#pragma unroll
        for (int kk = 0; kk < 16; kk++) {
            const ulonglong2 aA = *(const ulonglong2*)&As[cur][kk][tm];
            const ulonglong2 aB = *(const ulonglong2*)&As[cur][kk][tm + 4];
            const ulonglong2 p0 = *(const ulonglong2*)&Bs[cur][kk][tn];
            const ulonglong2 p1 = *(const ulonglong2*)&Bs[cur][kk][tn + 4];
            const ulonglong2 w0 = *(const ulonglong2*)&Bw[cur][kk][tn];
            const ulonglong2 w1 = *(const ulonglong2*)&Bw[cur][kk][tn + 4];
            const unsigned long long ap[4] = { aA.x, aA.y, aB.x, aB.y };
            const unsigned long long bp[4] = { p0.x, p0.y, p1.x, p1.y };
            const unsigned long long bw[4] = { w0.x, w0.y, w1.x, w1.y };
#pragma unroll
            for (int i = 0; i < 4; i++)
#pragma unroll
                for (int j = 0; j < 4; j++) {
                    ffma2(accd[i][j], ap[i], bp[j]);   // (r0c0, r1c1)
                    ffma2(accx[i][j], ap[i], bw[j]);   // (r0c1, r1c0)
                }
        }

        if (more) { STS_BLK((bk + 1) & 1); __syncthreads(); }
    }
#undef LDG_BLK
#undef STS_BLK

    // raw partial writes
#pragma unroll
    for (int i = 0; i < 4; i++) {
        const int r0 = tm + 2 * i;
#pragma unroll
        for (int j = 0; j < 4; j++) {
            const int c0 = n0 + tn + 2 * j;
            const float2 d = upk(accd[i][j]);
            const float2 x = upk(accx[i][j]);
            *(float2*)&P[(size_t)r0 * ldp + c0]       = make_float2(d.x, x.x);
            *(float2*)&P[(size_t)(r0 + 1) * ldp + c0] = make_float2(x.y, d.y);
        }
    }
}

// ------------------------------ persistent kernel ----------------------------
__global__ void __launch_bounds__(NTHR, 1)
persist_kernel(const float* __restrict__ z,
               const float* __restrict__ decW, const float* __restrict__ decb,
               const float* __restrict__ templ,
               const float* __restrict__ dW1, const float* __restrict__ db1,
               const float* __restrict__ dW2, const float* __restrict__ db2,
               const float* __restrict__ aW1, const float* __restrict__ ab1,
               const float* __restrict__ aW2, const float* __restrict__ ab2,
               const float* __restrict__ W1, const float* __restrict__ b1,
               const float* __restrict__ W2, const float* __restrict__ b2,
               float* __restrict__ out) {
    __shared__ __align__(16) float As[2][16][128];   // 16 KB
    __shared__ __align__(16) float Bs[2][16][128];   // 16 KB
    __shared__ __align__(16) float Bw[2][16][128];   // 16 KB  (48 KB total)

    const int cta = blockIdx.x;
    const int tid = threadIdx.x;
    float* sc = &As[0][0][0];   // prologue scratch overlays GEMM buffers

    // ---------------- P0: decoder GEMM (row = cta) --------------------------
    {
        if (tid < 128) sc[tid] = z[cta * 128 + tid];
        __syncthreads();
        for (int c = tid; c < 2048; c += NTHR) {
            float acc = decb[c];
#pragma unroll 8
            for (int k = 0; k < 128; k++) acc += sc[k] * decW[k * 2048 + c];
            g_embs[cta * 2048 + c] = acc;
        }
    }
    gridbar();

    // ---------------- P1: per-(batch,slot) init -> y0 + out[0] --------------
    {
        float* e   = sc;         // 64
        float* h   = sc + 64;    // 128
        float* ah  = sc + 192;   // 32
        float* alv = sc + 224;   // 1
        for (int job = cta; job < BATCH * 32; job += NCTA) {
            const int b = job >> 5;
            const int s = job & 31;
            if (tid < 64) e[tid] = __ldcg(&g_embs[b * 2048 + s * 64 + tid]);
            __syncthreads();
            if (tid < 128) {
                float acc = db1[tid];
#pragma unroll 8
                for (int i = 0; i < 64; i++) acc += e[i] * dW1[i * 128 + tid];
                h[tid] = fmaxf(acc, 0.f);
            }
            if (tid >= 128 && tid < 160) {
                const int t = tid - 128;
                float acc = ab1[t];
#pragma unroll 8
                for (int i = 0; i < 64; i++) acc += e[i] * aW1[i * 32 + t];
                ah[t] = fmaxf(acc, 0.f);
            }
            __syncthreads();
            if (tid == 0) {
                float l = ab2[0];
#pragma unroll
                for (int j = 0; j < 32; j++) l += ah[j] * aW2[j];
                alv[0] = 1.f / (1.f + expf(-l));
            }
            __syncthreads();
            const float alive = alv[0];
            if (tid < 99) {
                float acc = db2[tid] + templ[s * 99 + tid];
#pragma unroll 8
                for (int j = 0; j < 128; j++) acc += h[j] * dW2[j * 99 + tid];
                const float v = acc * alive;
                const int idx = b * STATE + s * 99 + tid;
                g_Y[idx] = v;
                out[idx] = v;
            }
            if (tid == 99) {
                const int idx = b * STATE + 3168 + s;
                g_Y[idx] = alive;
                out[idx] = alive;
            }
            __syncthreads();
        }
    }
    gridbar();

    // ---------------- main RK4 loop -----------------------------------------
    for (int s = 1; s < NSTEPS; s++) {
        float* so = out + (size_t)s * BATCH * STATE;

        for (int ev = 0; ev < 4; ev++) {
            const float* Ain = (ev == 0) ? g_Y : g_TMP;

            // ---- G1: 32 tiles x splitK4 = 128 jobs (K chunk 800 = 50 blocks)
            {
                const int tile = cta & 31;
                const int kq   = cta >> 5;
                gemm_job(Ain, STATE, W1, OHID, kq * 800, 50, tile * 128,
                         g_P1 + (size_t)kq * (BATCH * OHID), OHID, As, Bs, Bw);
            }
            gridbar();

            // ---- reduce: H = tanh(P0+P1+P2+P3+b1), row = cta
            {
                const int base = cta * OHID;
#pragma unroll
                for (int c = tid * 4; c < OHID; c += NTHR * 4) {
                    const float4 q0 = ldcg4(g_P1 + base + c);
                    const float4 q1 = ldcg4(g_P1 + 1 * BATCH * OHID + base + c);
                    const float4 q2 = ldcg4(g_P1 + 2 * BATCH * OHID + base + c);
                    const float4 q3 = ldcg4(g_P1 + 3 * BATCH * OHID + base + c);
                    const float4 bb = *(const float4*)(b1 + c);
                    float4 hv;
                    hv.x = tanhf(q0.x + q1.x + q2.x + q3.x + bb.x);
                    hv.y = tanhf(q0.y + q1.y + q2.y + q3.y + bb.y);
                    hv.z = tanhf(q0.z + q1.z + q2.z + q3.z + bb.z);
                    hv.w = tanhf(q0.w + q1.w + q2.w + q3.w + bb.w);
                    *(float4*)&g_H[base + c] = hv;
                }
            }
            gridbar();

            // ---- G2: 25 tiles x splitK4 = 100 jobs (K chunk 1024 = 64 blocks)
            if (cta < 100) {
                const int tile = cta % 25;
                const int kq   = cta / 25;
                gemm_job(g_H, OHID, W2, STATE, kq * 1024, 64, tile * 128,
                         g_P2 + (size_t)kq * (BATCH * STATE), STATE, As, Bs, Bw);
            }
            gridbar();

            // ---- update: k = sum(P)+b2 ; RK4 math, row = cta
            {
                const int base = cta * STATE;
                for (int c = tid * 4; c < STATE; c += NTHR * 4) {
                    const int i = base + c;
                    const float4 q0 = ldcg4(g_P2 + i);
                    const float4 q1 = ldcg4(g_P2 + 1 * BATCH * STATE + i);
                    const float4 q2 = ldcg4(g_P2 + 2 * BATCH * STATE + i);
                    const float4 q3 = ldcg4(g_P2 + 3 * BATCH * STATE + i);
                    const float4 bb = *(const float4*)(b2 + c);
                    float4 k;
                    k.x = q0.x + q1.x + q2.x + q3.x + bb.x;
                    k.y = q0.y + q1.y + q2.y + q3.y + bb.y;
                    k.z = q0.z + q1.z + q2.z + q3.z + bb.z;
                    k.w = q0.w + q1.w + q2.w + q3.w + bb.w;
                    const float4 y = *(const float4*)(g_Y + i);  // own row
                    if (ev == 0) {
                        *(float4*)&g_ACC[i] = k;
                        float4 t;
                        t.x = y.x + HDT * k.x; t.y = y.y + HDT * k.y;
                        t.z = y.z + HDT * k.z; t.w = y.w + HDT * k.w;
                        *(float4*)&g_TMP[i] = t;
                    } else if (ev == 1) {
                        float4 a = *(const float4*)&g_ACC[i];
                        a.x += 2.f * k.x; a.y += 2.f * k.y;
                        a.z += 2.f * k.z; a.w += 2.f * k.w;
                        *(float4*)&g_ACC[i] = a;
                        float4 t;
                        t.x = y.x + HDT * k.x; t.y = y.y + HDT * k.y;
                        t.z = y.z + HDT * k.z; t.w = y.w + HDT * k.w;
                        *(float4*)&g_TMP[i] = t;
                    } else if (ev == 2) {
                        float4 a = *(const float4*)&g_ACC[i];
                        a.x += 2.f * k.x; a.y += 2.f * k.y;
                        a.z += 2.f * k.z; a.w += 2.f * k.w;
                        *(float4*)&g_ACC[i] = a;
                        float4 t;
                        t.x = y.x + DT * k.x; t.y = y.y + DT * k.y;
                        t.z = y.z + DT * k.z; t.w = y.w + DT * k.w;
                        *(float4*)&g_TMP[i] = t;
                    } else {
                        const float4 a = *(const float4*)&g_ACC[i];
                        float4 yn;
                        yn.x = y.x + DT6 * (a.x + k.x);
                        yn.y = y.y + DT6 * (a.y + k.y);
                        yn.z = y.z + DT6 * (a.z + k.z);
                        yn.w = y.w + DT6 * (a.w + k.w);
                        *(float4*)&g_Y[i] = yn;
                        *(float4*)&so[i]  = yn;
                    }
                }
            }
            gridbar();
        }
    }
}

// ------------------------------ launcher ------------------------------------
extern "C" void kernel_launch(void* const* d_in, const int* in_sizes, int n_in,
                              void* d_out, int out_size) {
    (void)in_sizes; (void)n_in; (void)out_size;

    const float* z      = (const float*)d_in[0];
    const float* dec_W  = (const float*)d_in[1];
    const float* dec_b  = (const float*)d_in[2];
    const float* templ  = (const float*)d_in[3];
    const float* def_W1 = (const float*)d_in[4];
    const float* def_b1 = (const float*)d_in[5];
    const float* def_W2 = (const float*)d_in[6];
    const float* def_b2 = (const float*)d_in[7];
    const float* al_W1  = (const float*)d_in[8];
    const float* al_b1  = (const float*)d_in[9];
    const float* al_W2  = (const float*)d_in[10];
    const float* al_b2  = (const float*)d_in[11];
    const float* ode_W1 = (const float*)d_in[12];
    const float* ode_b1 = (const float*)d_in[13];
    const float* ode_W2 = (const float*)d_in[14];
    const float* ode_b2 = (const float*)d_in[15];
    float* out = (float*)d_out;

    persist_kernel<<<NCTA, NTHR>>>(z, dec_W, dec_b, templ,
                                   def_W1, def_b1, def_W2, def_b2,
                                   al_W1, al_b1, al_W2, al_b2,
                                   ode_W1, ode_b1, ode_W2, ode_b2, out);
}

// round 12
// speedup vs baseline: 1.0008x; 1.0008x over previous
#include <cuda_runtime.h>
#include <math.h>

// ---------------------------------------------------------------------------
// ONE persistent kernel = ONE graph node. 128 CTAs x 256 threads, co-resident
// (grid <= 148 SMs) -> software grid barrier.
//
// Per RK4 f-eval:
//   G1   : partials of A @ W1   (32 N-tiles(128) x split-K4 = 128 jobs)
//   redH : H = tanh(P0+P1+P2+P3+b1)
//   G2   : partials of H @ W2   (25 N-tiles(128) x split-K4 = 100 jobs)
//   upd  : k = sum(P)+b2 ; RK4 state update (+ trajectory store on k4)
//
// GEMM job: C(128x128), 256 threads (2 warps/SMSP for latency hiding),
// per-thread 8x8 via packed fma.rn.f32x2 with diag/anti-diag pairing.
// smem holds A[k][m], B[k][n], and a pair-swapped B copy, so ALL six operand
// groups load as natural ulonglong2 (LDS.128) -> zero packing MOVs.
// Double-buffered smem (48KB), one __syncthreads per 16-k block.
// Cross-CTA global reads use __ldcg (L1 incoherent within one launch).
// ---------------------------------------------------------------------------

#define BATCH   128
#define STATE   3200
#define OHID    4096
#define NSTEPS  192
#define NCTA    128
#define NTHR    256

constexpr float DT  = (float)(8.0 / 191.0);   // matches jnp f64->f32
constexpr float HDT = 0.5f * DT;
constexpr float DT6 = DT / 6.0f;

// -------------------- device scratch (no allocation allowed) ----------------
__device__ __align__(16) float g_embs[BATCH * 2048];
__device__ __align__(16) float g_Y   [BATCH * STATE];
__device__ __align__(16) float g_TMP [BATCH * STATE];
__device__ __align__(16) float g_ACC [BATCH * STATE];
__device__ __align__(16) float g_H   [BATCH * OHID];
__device__ __align__(16) float g_P1  [4 * BATCH * OHID];   // G1 split-K4 partials
__device__ __align__(16) float g_P2  [4 * BATCH * STATE];  // G2 split-K4 partials
__device__ unsigned          g_cnt;
__device__ volatile unsigned g_gen;

// ------------------------------- primitives ---------------------------------
__device__ __forceinline__ float2 upk(unsigned long long v) {
    float2 f;
    asm("mov.b64 {%0, %1}, %2;" : "=f"(f.x), "=f"(f.y) : "l"(v));
    return f;
}
__device__ __forceinline__ void ffma2(unsigned long long& d,
                                      unsigned long long a, unsigned long long b) {
    asm("fma.rn.f32x2 %0, %1, %2, %0;" : "+l"(d) : "l"(a), "l"(b));
}
__device__ __forceinline__ float4 ldcg4(const float* p) {
    return __ldcg(reinterpret_cast<const float4*>(p));
}

// Grid barrier: all 128 CTAs co-resident (1/SM). Fence by every thread makes
// this CTA's writes L2-visible before the arrival is published.
__device__ __forceinline__ void gridbar() {
    __threadfence();
    __syncthreads();
    if (threadIdx.x == 0) {
        const unsigned my = g_gen;
        if (atomicAdd(&g_cnt, 1u) == NCTA - 1u) {
            g_cnt = 0u;
            __threadfence();
            g_gen = my + 1u;
        } else {
            while (g_gen == my) { }
        }
        __threadfence();
    }
    __syncthreads();
}

// ------------------------------ GEMM tile job --------------------------------
// Partial C(128 x 128) = A[:, kbeg : kbeg+16*nblk] @ W[:, n0:n0+128] -> P (raw).
__device__ __forceinline__ void gemm_job(
    const float* __restrict__ A, int lda,
    const float* __restrict__ W, int ldw,
    int kbeg, int nblk, int n0,
    float* __restrict__ P, int ldp,
    float (&As)[2][16][128], float (&Bs)[2][16][128], float (&Bw)[2][16][128])
{
    const int tid = threadIdx.x;
    const int tm  = (tid >> 4) * 8;      // m base (0..120)
    const int tn  = (tid & 15) * 8;      // n base (0..120)
    // A staging: row = tid>>1 (0..127), k-half = (tid&1)*8
    const int arow = tid >> 1;
    const int akh  = (tid & 1) * 8;
    // B staging: k-row = tid>>4 (0..15), col base = (tid&15)*8
    const int brow = tid >> 4;
    const int bcol = (tid & 15) * 8;

    const float* Ap = A + (size_t)arow * lda + kbeg + akh;
    const float* Wp = W + (size_t)(kbeg + brow) * ldw + n0 + bcol;
    const size_t wstep = (size_t)16 * ldw;

    unsigned long long accd[4][4], accx[4][4];
#pragma unroll
    for (int i = 0; i < 4; i++)
#pragma unroll
        for (int j = 0; j < 4; j++) { accd[i][j] = 0ull; accx[i][j] = 0ull; }

    float4 a0, a1, b0, b1;

#define LDG_BLK(bk)                                                \
    do {                                                           \
        const float* Aq = Ap + (bk) * 16;                          \
        a0 = ldcg4(Aq);  a1 = ldcg4(Aq + 4);                       \
        const float* Wq = Wp + (size_t)(bk) * wstep;               \
        b0 = *(const float4*)Wq;                                   \
        b1 = *(const float4*)(Wq + 4);                             \
    } while (0)

#define STS_BLK(nb)                                                \
    do {                                                           \
        As[nb][akh + 0][arow] = a0.x; As[nb][akh + 1][arow] = a0.y;\
        As[nb][akh + 2][arow] = a0.z; As[nb][akh + 3][arow] = a0.w;\
        As[nb][akh + 4][arow] = a1.x; As[nb][akh + 5][arow] = a1.y;\
        As[nb][akh + 6][arow] = a1.z; As[nb][akh + 7][arow] = a1.w;\
        *(float4*)&Bs[nb][brow][bcol]     = b0;                    \
        *(float4*)&Bs[nb][brow][bcol + 4] = b1;                    \
        *(float4*)&Bw[nb][brow][bcol]     = make_float4(b0.y, b0.x, b0.w, b0.z); \
        *(float4*)&Bw[nb][brow][bcol + 4] = make_float4(b1.y, b1.x, b1.w, b1.z); \
    } while (0)

    LDG_BLK(0);
    STS_BLK(0);
    __syncthreads();

    for (int bk = 0; bk < nblk; bk++) {
        const int cur = bk & 1;
        const bool more = (bk + 1) < nblk;
        if (more) LDG_BLK(bk + 1);

#pragma unroll
        for (int kk = 0; kk < 16; kk++) {
            const ulonglong2 aA = *(const ulonglong2*)&As[cur][kk][tm];
            const ulonglong2 aB = *(const ulonglong2*)&As[cur][kk][tm + 4];
            const ulonglong2 p0 = *(const ulonglong2*)&Bs[cur][kk][tn];
            const ulonglong2 p1 = *(const ulonglong2*)&Bs[cur][kk][tn + 4];
            const ulonglong2 w0 = *(const ulonglong2*)&Bw[cur][kk][tn];
            const ulonglong2 w1 = *(const ulonglong2*)&Bw[cur][kk][tn + 4];
            const unsigned long long ap[4] = { aA.x, aA.y, aB.x, aB.y };
            const unsigned long long bp[4] = { p0.x, p0.y, p1.x, p1.y };
            const unsigned long long bw[4] = { w0.x, w0.y, w1.x, w1.y };
#pragma unroll
            for (int i = 0; i < 4; i++)
#pragma unroll
                for (int j = 0; j < 4; j++) {
                    ffma2(accd[i][j], ap[i], bp[j]);   // (r0c0, r1c1)
                    ffma2(accx[i][j], ap[i], bw[j]);   // (r0c1, r1c0)
                }
        }

        if (more) { STS_BLK((bk + 1) & 1); __syncthreads(); }
    }
#undef LDG_BLK
#undef STS_BLK

    // raw partial writes
#pragma unroll
    for (int i = 0; i < 4; i++) {
        const int r0 = tm + 2 * i;
#pragma unroll
        for (int j = 0; j < 4; j++) {
            const int c0 = n0 + tn + 2 * j;
            const float2 d = upk(accd[i][j]);
            const float2 x = upk(accx[i][j]);
            *(float2*)&P[(size_t)r0 * ldp + c0]       = make_float2(d.x, x.x);
            *(float2*)&P[(size_t)(r0 + 1) * ldp + c0] = make_float2(x.y, d.y);
        }
    }
}

// ------------------------------ persistent kernel ----------------------------
__global__ void __launch_bounds__(NTHR, 1)
persist_kernel(const float* __restrict__ z,
               const float* __restrict__ decW, const float* __restrict__ decb,
               const float* __restrict__ templ,
               const float* __restrict__ dW1, const float* __restrict__ db1,
               const float* __restrict__ dW2, const float* __restrict__ db2,
               const float* __restrict__ aW1, const float* __restrict__ ab1,
               const float* __restrict__ aW2, const float* __restrict__ ab2,
               const float* __restrict__ W1, const float* __restrict__ b1,
               const float* __restrict__ W2, const float* __restrict__ b2,
               float* __restrict__ out) {
    __shared__ __align__(16) float As[2][16][128];   // 16 KB
    __shared__ __align__(16) float Bs[2][16][128];   // 16 KB
    __shared__ __align__(16) float Bw[2][16][128];   // 16 KB  (48 KB total)

    const int cta = blockIdx.x;
    const int tid = threadIdx.x;
    float* sc = &As[0][0][0];   // prologue scratch overlays GEMM buffers

    // ---------------- P0: decoder GEMM (row = cta) --------------------------
    {
        if (tid < 128) sc[tid] = z[cta * 128 + tid];
        __syncthreads();
        for (int c = tid; c < 2048; c += NTHR) {
            float acc = decb[c];
#pragma unroll 8
            for (int k = 0; k < 128; k++) acc += sc[k] * decW[k * 2048 + c];
            g_embs[cta * 2048 + c] = acc;
        }
    }
    gridbar();

    // ---------------- P1: per-(batch,slot) init -> y0 + out[0] --------------
    {
        float* e   = sc;         // 64
        float* h   = sc + 64;    // 128
        float* ah  = sc + 192;   // 32
        float* alv = sc + 224;   // 1
        for (int job = cta; job < BATCH * 32; job += NCTA) {
            const int b = job >> 5;
            const int s = job & 31;
            if (tid < 64) e[tid] = __ldcg(&g_embs[b * 2048 + s * 64 + tid]);
            __syncthreads();
            if (tid < 128) {
                float acc = db1[tid];
#pragma unroll 8
                for (int i = 0; i < 64; i++) acc += e[i] * dW1[i * 128 + tid];
                h[tid] = fmaxf(acc, 0.f);
            }
            if (tid >= 128 && tid < 160) {
                const int t = tid - 128;
                float acc = ab1[t];
#pragma unroll 8
                for (int i = 0; i < 64; i++) acc += e[i] * aW1[i * 32 + t];
                ah[t] = fmaxf(acc, 0.f);
            }
            __syncthreads();
            if (tid == 0) {
                float l = ab2[0];
#pragma unroll
                for (int j = 0; j < 32; j++) l += ah[j] * aW2[j];
                alv[0] = 1.f / (1.f + expf(-l));
            }
            __syncthreads();
            const float alive = alv[0];
            if (tid < 99) {
                float acc = db2[tid] + templ[s * 99 + tid];
#pragma unroll 8
                for (int j = 0; j < 128; j++) acc += h[j] * dW2[j * 99 + tid];
                const float v = acc * alive;
                const int idx = b * STATE + s * 99 + tid;
                g_Y[idx] = v;
                out[idx] = v;
            }
            if (tid == 99) {
                const int idx = b * STATE + 3168 + s;
                g_Y[idx] = alive;
                out[idx] = alive;
            }
            __syncthreads();
        }
    }
    gridbar();

    // ---------------- main RK4 loop -----------------------------------------
    for (int s = 1; s < NSTEPS; s++) {
        float* so = out + (size_t)s * BATCH * STATE;

        for (int ev = 0; ev < 4; ev++) {
            const float* Ain = (ev == 0) ? g_Y : g_TMP;

            // ---- G1: 32 tiles x splitK4 = 128 jobs (K chunk 800 = 50 blocks)
            {
                const int tile = cta & 31;
                const int kq   = cta >> 5;
                gemm_job(Ain, STATE, W1, OHID, kq * 800, 50, tile * 128,
                         g_P1 + (size_t)kq * (BATCH * OHID), OHID, As, Bs, Bw);
            }
            gridbar();

            // ---- reduce: H = tanh(P0+P1+P2+P3+b1), row = cta
            {
                const int base = cta * OHID;
#pragma unroll
                for (int c = tid * 4; c < OHID; c += NTHR * 4) {
                    const float4 q0 = ldcg4(g_P1 + base + c);
                    const float4 q1 = ldcg4(g_P1 + 1 * BATCH * OHID + base + c);
                    const float4 q2 = ldcg4(g_P1 + 2 * BATCH * OHID + base + c);
                    const float4 q3 = ldcg4(g_P1 + 3 * BATCH * OHID + base + c);
                    const float4 bb = *(const float4*)(b1 + c);
                    float4 hv;
                    hv.x = tanhf(q0.x + q1.x + q2.x + q3.x + bb.x);
                    hv.y = tanhf(q0.y + q1.y + q2.y + q3.y + bb.y);
                    hv.z = tanhf(q0.z + q1.z + q2.z + q3.z + bb.z);
                    hv.w = tanhf(q0.w + q1.w + q2.w + q3.w + bb.w);
                    *(float4*)&g_H[base + c] = hv;
                }
            }
            gridbar();

            // ---- G2: 25 tiles x splitK4 = 100 jobs (K chunk 1024 = 64 blocks)
            if (cta < 100) {
                const int tile = cta % 25;
                const int kq   = cta / 25;
                gemm_job(g_H, OHID, W2, STATE, kq * 1024, 64, tile * 128,
                         g_P2 + (size_t)kq * (BATCH * STATE), STATE, As, Bs, Bw);
            }
            gridbar();

            // ---- update: k = sum(P)+b2 ; RK4 math, row = cta
            {
                const int base = cta * STATE;
                for (int c = tid * 4; c < STATE; c += NTHR * 4) {
                    const int i = base + c;
                    const float4 q0 = ldcg4(g_P2 + i);
                    const float4 q1 = ldcg4(g_P2 + 1 * BATCH * STATE + i);
                    const float4 q2 = ldcg4(g_P2 + 2 * BATCH * STATE + i);
                    const float4 q3 = ldcg4(g_P2 + 3 * BATCH * STATE + i);
                    const float4 bb = *(const float4*)(b2 + c);
                    float4 k;
                    k.x = q0.x + q1.x + q2.x + q3.x + bb.x;
                    k.y = q0.y + q1.y + q2.y + q3.y + bb.y;
                    k.z = q0.z + q1.z + q2.z + q3.z + bb.z;
                    k.w = q0.w + q1.w + q2.w + q3.w + bb.w;
                    const float4 y = *(const float4*)(g_Y + i);  // own row
                    if (ev == 0) {
                        *(float4*)&g_ACC[i] = k;
                        float4 t;
                        t.x = y.x + HDT * k.x; t.y = y.y + HDT * k.y;
                        t.z = y.z + HDT * k.z; t.w = y.w + HDT * k.w;
                        *(float4*)&g_TMP[i] = t;
                    } else if (ev == 1) {
                        float4 a = *(const float4*)&g_ACC[i];
                        a.x += 2.f * k.x; a.y += 2.f * k.y;
                        a.z += 2.f * k.z; a.w += 2.f * k.w;
                        *(float4*)&g_ACC[i] = a;
                        float4 t;
                        t.x = y.x + HDT * k.x; t.y = y.y + HDT * k.y;
                        t.z = y.z + HDT * k.z; t.w = y.w + HDT * k.w;
                        *(float4*)&g_TMP[i] = t;
                    } else if (ev == 2) {
                        float4 a = *(const float4*)&g_ACC[i];
                        a.x += 2.f * k.x; a.y += 2.f * k.y;
                        a.z += 2.f * k.z; a.w += 2.f * k.w;
                        *(float4*)&g_ACC[i] = a;
                        float4 t;
                        t.x = y.x + DT * k.x; t.y = y.y + DT * k.y;
                        t.z = y.z + DT * k.z; t.w = y.w + DT * k.w;
                        *(float4*)&g_TMP[i] = t;
                    } else {
                        const float4 a = *(const float4*)&g_ACC[i];
                        float4 yn;
                        yn.x = y.x + DT6 * (a.x + k.x);
                        yn.y = y.y + DT6 * (a.y + k.y);
                        yn.z = y.z + DT6 * (a.z + k.z);
                        yn.w = y.w + DT6 * (a.w + k.w);
                        *(float4*)&g_Y[i] = yn;
                        *(float4*)&so[i]  = yn;
                    }
                }
            }
            gridbar();
        }
    }
}

// ------------------------------ launcher ------------------------------------
extern "C" void kernel_launch(void* const* d_in, const int* in_sizes, int n_in,
                              void* d_out, int out_size) {
    (void)in_sizes; (void)n_in; (void)out_size;

    const float* z      = (const float*)d_in[0];
    const float* dec_W  = (const float*)d_in[1];
    const float* dec_b  = (const float*)d_in[2];
    const float* templ  = (const float*)d_in[3];
    const float* def_W1 = (const float*)d_in[4];
    const float* def_b1 = (const float*)d_in[5];
    const float* def_W2 = (const float*)d_in[6];
    const float* def_b2 = (const float*)d_in[7];
    const float* al_W1  = (const float*)d_in[8];
    const float* al_b1  = (const float*)d_in[9];
    const float* al_W2  = (const float*)d_in[10];
    const float* al_b2  = (const float*)d_in[11];
    const float* ode_W1 = (const float*)d_in[12];
    const float* ode_b1 = (const float*)d_in[13];
    const float* ode_W2 = (const float*)d_in[14];
    const float* ode_b2 = (const float*)d_in[15];
    float* out = (float*)d_out;

    persist_kernel<<<NCTA, NTHR>>>(z, dec_W, dec_b, templ,
                                   def_W1, def_b1, def_W2, def_b2,
                                   al_W1, al_b1, al_W2, al_b2,
                                   ode_W1, ode_b1, ode_W2, ode_b2, out);
}

// round 13
// speedup vs baseline: 1.0015x; 1.0007x over previous
#include <cuda_runtime.h>
#include <math.h>

// ---------------------------------------------------------------------------
// ONE persistent kernel = ONE graph node. 128 CTAs x 256 threads, co-resident
// (grid <= 148 SMs) -> software grid barrier.
//
// Per RK4 f-eval:
//   G1   : partials of A @ W1   (32 N-tiles(128) x split-K4 = 128 jobs)
//   redH : H = tanh(P0+P1+P2+P3+b1)
//   G2   : partials of H @ W2   (25 N-tiles(128) x split-K4 = 100 jobs)
//   upd  : k = sum(P)+b2 ; RK4 state update (+ trajectory store on k4)
//
// GEMM job: C(128x128), 256 threads (2 warps/SMSP for latency hiding),
// per-thread 8x8 via packed fma.rn.f32x2 with diag/anti-diag pairing.
// smem holds A[k][m], B[k][n], and a pair-swapped B copy, so ALL six operand
// groups load as natural ulonglong2 (LDS.128) -> zero packing MOVs.
// Double-buffered smem (48KB), one __syncthreads per 16-k block.
// Cross-CTA global reads use __ldcg (L1 incoherent within one launch).
// ---------------------------------------------------------------------------

#define BATCH   128
#define STATE   3200
#define OHID    4096
#define NSTEPS  192
#define NCTA    128
#define NTHR    256

constexpr float DT  = (float)(8.0 / 191.0);   // matches jnp f64->f32
constexpr float HDT = 0.5f * DT;
constexpr float DT6 = DT / 6.0f;

// -------------------- device scratch (no allocation allowed) ----------------
__device__ __align__(16) float g_embs[BATCH * 2048];
__device__ __align__(16) float g_Y   [BATCH * STATE];
__device__ __align__(16) float g_TMP [BATCH * STATE];
__device__ __align__(16) float g_ACC [BATCH * STATE];
__device__ __align__(16) float g_H   [BATCH * OHID];
__device__ __align__(16) float g_P1  [4 * BATCH * OHID];   // G1 split-K4 partials
__device__ __align__(16) float g_P2  [4 * BATCH * STATE];  // G2 split-K4 partials
__device__ unsigned          g_cnt;
__device__ volatile unsigned g_gen;

// ------------------------------- primitives ---------------------------------
__device__ __forceinline__ float2 upk(unsigned long long v) {
    float2 f;
    asm("mov.b64 {%0, %1}, %2;" : "=f"(f.x), "=f"(f.y) : "l"(v));
    return f;
}
__device__ __forceinline__ void ffma2(unsigned long long& d,
                                      unsigned long long a, unsigned long long b) {
    asm("fma.rn.f32x2 %0, %1, %2, %0;" : "+l"(d) : "l"(a), "l"(b));
}
__device__ __forceinline__ float4 ldcg4(const float* p) {
    return __ldcg(reinterpret_cast<const float4*>(p));
}

// Grid barrier: all 128 CTAs co-resident (1/SM). Fence by every thread makes
// this CTA's writes L2-visible before the arrival is published.
__device__ __forceinline__ void gridbar() {
    __threadfence();
    __syncthreads();
    if (threadIdx.x == 0) {
        const unsigned my = g_gen;
        if (atomicAdd(&g_cnt, 1u) == NCTA - 1u) {
            g_cnt = 0u;
            __threadfence();
            g_gen = my + 1u;
        } else {
            while (g_gen == my) { }
        }
        __threadfence();
    }
    __syncthreads();
}

// ------------------------------ GEMM tile job --------------------------------
// Partial C(128 x 128) = A[:, kbeg : kbeg+16*nblk] @ W[:, n0:n0+128] -> P (raw).
__device__ __forceinline__ void gemm_job(
    const float* __restrict__ A, int lda,
    const float* __restrict__ W, int ldw,
    int kbeg, int nblk, int n0,
    float* __restrict__ P, int ldp,
    float (&As)[2][16][128], float (&Bs)[2][16][128], float (&Bw)[2][16][128])
{
    const int tid = threadIdx.x;
    const int tm  = (tid >> 4) * 8;      // m base (0..120)
    const int tn  = (tid & 15) * 8;      // n base (0..120)
    // A staging: row = tid>>1 (0..127), k-half = (tid&1)*8
    const int arow = tid >> 1;
    const int akh  = (tid & 1) * 8;
    // B staging: k-row = tid>>4 (0..15), col base = (tid&15)*8
    const int brow = tid >> 4;
    const int bcol = (tid & 15) * 8;

    const float* Ap = A + (size_t)arow * lda + kbeg + akh;
    const float* Wp = W + (size_t)(kbeg + brow) * ldw + n0 + bcol;
    const size_t wstep = (size_t)16 * ldw;

    unsigned long long accd[4][4], accx[4][4];
#pragma unroll
    for (int i = 0; i < 4; i++)
#pragma unroll
        for (int j = 0; j < 4; j++) { accd[i][j] = 0ull; accx[i][j] = 0ull; }

    float4 a0, a1, b0, b1;

#define LDG_BLK(bk)                                                \
    do {                                                           \
        const float* Aq = Ap + (bk) * 16;                          \
        a0 = ldcg4(Aq);  a1 = ldcg4(Aq + 4);                       \
        const float* Wq = Wp + (size_t)(bk) * wstep;               \
        b0 = *(const float4*)Wq;                                   \
        b1 = *(const float4*)(Wq + 4);                             \
    } while (0)

#define STS_BLK(nb)                                                \
    do {                                                           \
        As[nb][akh + 0][arow] = a0.x; As[nb][akh + 1][arow] = a0.y;\
        As[nb][akh + 2][arow] = a0.z; As[nb][akh + 3][arow] = a0.w;\
        As[nb][akh + 4][arow] = a1.x; As[nb][akh + 5][arow] = a1.y;\
        As[nb][akh + 6][arow] = a1.z; As[nb][akh + 7][arow] = a1.w;\
        *(float4*)&Bs[nb][brow][bcol]     = b0;                    \
        *(float4*)&Bs[nb][brow][bcol + 4] = b1;                    \
        *(float4*)&Bw[nb][brow][bcol]     = make_float4(b0.y, b0.x, b0.w, b0.z); \
        *(float4*)&Bw[nb][brow][bcol + 4] = make_float4(b1.y, b1.x, b1.w, b1.z); \
    } while (0)

    LDG_BLK(0);
    STS_BLK(0);
    __syncthreads();

    for (int bk = 0; bk < nblk; bk++) {
        const int cur = bk & 1;
        const bool more = (bk + 1) < nblk;
        if (more) LDG_BLK(bk + 1);

#pragma unroll
        for (int kk = 0; kk < 16; kk++) {
            const ulonglong2 aA = *(const ulonglong2*)&As[cur][kk][tm];
            const ulonglong2 aB = *(const ulonglong2*)&As[cur][kk][tm + 4];
            const ulonglong2 p0 = *(const ulonglong2*)&Bs[cur][kk][tn];
            const ulonglong2 p1 = *(const ulonglong2*)&Bs[cur][kk][tn + 4];
            const ulonglong2 w0 = *(const ulonglong2*)&Bw[cur][kk][tn];
            const ulonglong2 w1 = *(const ulonglong2*)&Bw[cur][kk][tn + 4];
            const unsigned long long ap[4] = { aA.x, aA.y, aB.x, aB.y };
            const unsigned long long bp[4] = { p0.x, p0.y, p1.x, p1.y };
            const unsigned long long bw[4] = { w0.x, w0.y, w1.x, w1.y };
#pragma unroll
            for (int i = 0; i < 4; i++)
#pragma unroll
                for (int j = 0; j < 4; j++) {
                    ffma2(accd[i][j], ap[i], bp[j]);   // (r0c0, r1c1)
                    ffma2(accx[i][j], ap[i], bw[j]);   // (r0c1, r1c0)
                }
        }

        if (more) { STS_BLK((bk + 1) & 1); __syncthreads(); }
    }
#undef LDG_BLK
#undef STS_BLK

    // raw partial writes
#pragma unroll
    for (int i = 0; i < 4; i++) {
        const int r0 = tm + 2 * i;
#pragma unroll
        for (int j = 0; j < 4; j++) {
            const int c0 = n0 + tn + 2 * j;
            const float2 d = upk(accd[i][j]);
            const float2 x = upk(accx[i][j]);
            *(float2*)&P[(size_t)r0 * ldp + c0]       = make_float2(d.x, x.x);
            *(float2*)&P[(size_t)(r0 + 1) * ldp + c0] = make_float2(x.y, d.y);
        }
    }
}

// ------------------------------ persistent kernel ----------------------------
__global__ void __launch_bounds__(NTHR, 1)
persist_kernel(const float* __restrict__ z,
               const float* __restrict__ decW, const float* __restrict__ decb,
               const float* __restrict__ templ,
               const float* __restrict__ dW1, const float* __restrict__ db1,
               const float* __restrict__ dW2, const float* __restrict__ db2,
               const float* __restrict__ aW1, const float* __restrict__ ab1,
               const float* __restrict__ aW2, const float* __restrict__ ab2,
               const float* __restrict__ W1, const float* __restrict__ b1,
               const float* __restrict__ W2, const float* __restrict__ b2,
               float* __restrict__ out) {
    __shared__ __align__(16) float As[2][16][128];   // 16 KB
    __shared__ __align__(16) float Bs[2][16][128];   // 16 KB
    __shared__ __align__(16) float Bw[2][16][128];   // 16 KB  (48 KB total)

    const int cta = blockIdx.x;
    const int tid = threadIdx.x;
    float* sc = &As[0][0][0];   // prologue scratch overlays GEMM buffers

    // ---------------- P0: decoder GEMM (row = cta) --------------------------
    {
        if (tid < 128) sc[tid] = z[cta * 128 + tid];
        __syncthreads();
        for (int c = tid; c < 2048; c += NTHR) {
            float acc = decb[c];
#pragma unroll 8
            for (int k = 0; k < 128; k++) acc += sc[k] * decW[k * 2048 + c];
            g_embs[cta * 2048 + c] = acc;
        }
    }
    gridbar();

    // ---------------- P1: per-(batch,slot) init -> y0 + out[0] --------------
    {
        float* e   = sc;         // 64
        float* h   = sc + 64;    // 128
        float* ah  = sc + 192;   // 32
        float* alv = sc + 224;   // 1
        for (int job = cta; job < BATCH * 32; job += NCTA) {
            const int b = job >> 5;
            const int s = job & 31;
            if (tid < 64) e[tid] = __ldcg(&g_embs[b * 2048 + s * 64 + tid]);
            __syncthreads();
            if (tid < 128) {
                float acc = db1[tid];
#pragma unroll 8
                for (int i = 0; i < 64; i++) acc += e[i] * dW1[i * 128 + tid];
                h[tid] = fmaxf(acc, 0.f);
            }
            if (tid >= 128 && tid < 160) {
                const int t = tid - 128;
                float acc = ab1[t];
#pragma unroll 8
                for (int i = 0; i < 64; i++) acc += e[i] * aW1[i * 32 + t];
                ah[t] = fmaxf(acc, 0.f);
            }
            __syncthreads();
            if (tid == 0) {
                float l = ab2[0];
#pragma unroll
                for (int j = 0; j < 32; j++) l += ah[j] * aW2[j];
                alv[0] = 1.f / (1.f + expf(-l));
            }
            __syncthreads();
            const float alive = alv[0];
            if (tid < 99) {
                float acc = db2[tid] + templ[s * 99 + tid];
#pragma unroll 8
                for (int j = 0; j < 128; j++) acc += h[j] * dW2[j * 99 + tid];
                const float v = acc * alive;
                const int idx = b * STATE + s * 99 + tid;
                g_Y[idx] = v;
                out[idx] = v;
            }
            if (tid == 99) {
                const int idx = b * STATE + 3168 + s;
                g_Y[idx] = alive;
                out[idx] = alive;
            }
            __syncthreads();
        }
    }
    gridbar();

    // ---------------- main RK4 loop -----------------------------------------
    for (int s = 1; s < NSTEPS; s++) {
        float* so = out + (size_t)s * BATCH * STATE;

        for (int ev = 0; ev < 4; ev++) {
            const float* Ain = (ev == 0) ? g_Y : g_TMP;

            // ---- G1: 32 tiles x splitK4 = 128 jobs (K chunk 800 = 50 blocks)
            {
                const int tile = cta & 31;
                const int kq   = cta >> 5;
                gemm_job(Ain, STATE, W1, OHID, kq * 800, 50, tile * 128,
                         g_P1 + (size_t)kq * (BATCH * OHID), OHID, As, Bs, Bw);
            }
            gridbar();

            // ---- reduce: H = tanh(P0+P1+P2+P3+b1), row = cta
            {
                const int base = cta * OHID;
#pragma unroll
                for (int c = tid * 4; c < OHID; c += NTHR * 4) {
                    const float4 q0 = ldcg4(g_P1 + base + c);
                    const float4 q1 = ldcg4(g_P1 + 1 * BATCH * OHID + base + c);
                    const float4 q2 = ldcg4(g_P1 + 2 * BATCH * OHID + base + c);
                    const float4 q3 = ldcg4(g_P1 + 3 * BATCH * OHID + base + c);
                    const float4 bb = *(const float4*)(b1 + c);
                    float4 hv;
                    hv.x = tanhf(q0.x + q1.x + q2.x + q3.x + bb.x);
                    hv.y = tanhf(q0.y + q1.y + q2.y + q3.y + bb.y);
                    hv.z = tanhf(q0.z + q1.z + q2.z + q3.z + bb.z);
                    hv.w = tanhf(q0.w + q1.w + q2.w + q3.w + bb.w);
                    *(float4*)&g_H[base + c] = hv;
                }
            }
            gridbar();

            // ---- G2: 25 tiles x splitK4 = 100 jobs (K chunk 1024 = 64 blocks)
            if (cta < 100) {
                const int tile = cta % 25;
                const int kq   = cta / 25;
                gemm_job(g_H, OHID, W2, STATE, kq * 1024, 64, tile * 128,
                         g_P2 + (size_t)kq * (BATCH * STATE), STATE, As, Bs, Bw);
            }
            gridbar();

            // ---- update: k = sum(P)+b2 ; RK4 math, row = cta
            {
                const int base = cta * STATE;
                for (int c = tid * 4; c < STATE; c += NTHR * 4) {
                    const int i = base + c;
                    const float4 q0 = ldcg4(g_P2 + i);
                    const float4 q1 = ldcg4(g_P2 + 1 * BATCH * STATE + i);
                    const float4 q2 = ldcg4(g_P2 + 2 * BATCH * STATE + i);
                    const float4 q3 = ldcg4(g_P2 + 3 * BATCH * STATE + i);
                    const float4 bb = *(const float4*)(b2 + c);
                    float4 k;
                    k.x = q0.x + q1.x + q2.x + q3.x + bb.x;
                    k.y = q0.y + q1.y + q2.y + q3.y + bb.y;
                    k.z = q0.z + q1.z + q2.z + q3.z + bb.z;
                    k.w = q0.w + q1.w + q2.w + q3.w + bb.w;
                    const float4 y = *(const float4*)(g_Y + i);  // own row
                    if (ev == 0) {
                        *(float4*)&g_ACC[i] = k;
                        float4 t;
                        t.x = y.x + HDT * k.x; t.y = y.y + HDT * k.y;
                        t.z = y.z + HDT * k.z; t.w = y.w + HDT * k.w;
                        *(float4*)&g_TMP[i] = t;
                    } else if (ev == 1) {
                        float4 a = *(const float4*)&g_ACC[i];
                        a.x += 2.f * k.x; a.y += 2.f * k.y;
                        a.z += 2.f * k.z; a.w += 2.f * k.w;
                        *(float4*)&g_ACC[i] = a;
                        float4 t;
                        t.x = y.x + HDT * k.x; t.y = y.y + HDT * k.y;
                        t.z = y.z + HDT * k.z; t.w = y.w + HDT * k.w;
                        *(float4*)&g_TMP[i] = t;
                    } else if (ev == 2) {
                        float4 a = *(const float4*)&g_ACC[i];
                        a.x += 2.f * k.x; a.y += 2.f * k.y;
                        a.z += 2.f * k.z; a.w += 2.f * k.w;
                        *(float4*)&g_ACC[i] = a;
                        float4 t;
                        t.x = y.x + DT * k.x; t.y = y.y + DT * k.y;
                        t.z = y.z + DT * k.z; t.w = y.w + DT * k.w;
                        *(float4*)&g_TMP[i] = t;
                    } else {
                        const float4 a = *(const float4*)&g_ACC[i];
                        float4 yn;
                        yn.x = y.x + DT6 * (a.x + k.x);
                        yn.y = y.y + DT6 * (a.y + k.y);
                        yn.z = y.z + DT6 * (a.z + k.z);
                        yn.w = y.w + DT6 * (a.w + k.w);
                        *(float4*)&g_Y[i] = yn;
                        *(float4*)&so[i]  = yn;
                    }
                }
            }
            gridbar();
        }
    }
}

// ------------------------------ launcher ------------------------------------
extern "C" void kernel_launch(void* const* d_in, const int* in_sizes, int n_in,
                              void* d_out, int out_size) {
    (void)in_sizes; (void)n_in; (void)out_size;

    const float* z      = (const float*)d_in[0];
    const float* dec_W  = (const float*)d_in[1];
    const float* dec_b  = (const float*)d_in[2];
    const float* templ  = (const float*)d_in[3];
    const float* def_W1 = (const float*)d_in[4];
    const float* def_b1 = (const float*)d_in[5];
    const float* def_W2 = (const float*)d_in[6];
    const float* def_b2 = (const float*)d_in[7];
    const float* al_W1  = (const float*)d_in[8];
    const float* al_b1  = (const float*)d_in[9];
    const float* al_W2  = (const float*)d_in[10];
    const float* al_b2  = (const float*)d_in[11];
    const float* ode_W1 = (const float*)d_in[12];
    const float* ode_b1 = (const float*)d_in[13];
    const float* ode_W2 = (const float*)d_in[14];
    const float* ode_b2 = (const float*)d_in[15];
    float* out = (float*)d_out;

    persist_kernel<<<NCTA, NTHR>>>(z, dec_W, dec_b, templ,
                                   def_W1, def_b1, def_W2, def_b2,
                                   al_W1, al_b1, al_W2, al_b2,
                                   ode_W1, ode_b1, ode_W2, ode_b2, out);
}